// round 14
// baseline (speedup 1.0000x reference)
#include <cuda_runtime.h>
#include <cstdint>
#include <cstddef>

#define T_STEPS 1024
#define BATCH   128
#define INDIM   100
#define HID     200
#define NCLS    100
#define NBG     8
#define MB      16
#define NHG     17
#define NHU     12
#define NG      48
#define NTHR    768
#define NCTA    (NBG*NHG)   // 136
#define XSTR    20
#define GRS     18
#define GBS     (NG*GRS)    // 864
#define XPROWS  816         // 4 gates * 204

#define HN_OFF  (T_STEPS*BATCH*NCLS)
#define CN_OFF  (HN_OFF + 2*BATCH*HID)

// ---- smem float offsets ----
#define OFF_W0  0                        // W0 transposed [300][48]
#define OFF_W1  14400                    // W1 transposed [400][48]
#define OFF_XH  33600                    // [500][XSTR]; prepass reuses as [6][100][16]
#define OFF_GB0 43600                    // [4][GBS]; prepass uses [12][GBS] from here
#define OFF_GB1 47056                    // [8][GBS]
#define OFF_B0  57424
#define OFF_B1  57472
#define OFF_C0  57520
#define OFF_C1  57712
#define SMEM_FLOATS 57920
#define SMEM_BYTES  (SMEM_FLOATS*4)      // 231,680 B

// FC-phase smem reuse
#define OFF_FW  0
#define OFF_FB  20000
#define OFF_YS  20128

__device__ __align__(256) float g_ph0[2][HID*BATCH];
__device__ __align__(256) float g_ph1[2][HID*BATCH];
__device__ __align__(256) float g_y1[(size_t)T_STEPS*HID*BATCH];
__device__ __align__(256) float g_xp[(size_t)T_STEPS*XPROWS*BATCH];  // x-projection
__device__ unsigned g_bar[NBG*32];
__device__ unsigned g_gbar;
__device__ unsigned g_ack;

__device__ __forceinline__ float tanha(float x) {
    float r;
    asm("tanh.approx.f32 %0, %1;" : "=f"(r) : "f"(x));
    return r;
}
__device__ __forceinline__ float sigm(float x) {
    return fmaf(0.5f, tanha(0.5f * x), 0.5f);
}
__device__ __forceinline__ void bar_arrive(unsigned* p) {
    unsigned one = 1u;
    asm volatile("red.release.gpu.global.add.u32 [%0], %1;" :: "l"(p), "r"(one) : "memory");
}
__device__ __forceinline__ unsigned ld_acq(const unsigned* p) {
    unsigned v;
    asm volatile("ld.acquire.gpu.global.u32 %0, [%1];" : "=r"(v) : "l"(p) : "memory");
    return v;
}
__device__ __forceinline__ void cpa16(uint32_t dst, const void* src) {
    asm volatile("cp.async.cg.shared.global [%0], [%1], 16;" :: "r"(dst), "l"(src) : "memory");
}
#define CPA_COMMIT() asm volatile("cp.async.commit_group;" ::: "memory")
#define CPA_WAIT0()  asm volatile("cp.async.wait_group 0;" ::: "memory")

#define FMA2(acc, w, x) \
    asm("fma.rn.f32x2 %0, %1, %2, %0;" : "+l"(acc) : "l"(w), "l"(x))
__device__ __forceinline__ unsigned long long pk2(unsigned lo, unsigned hi) {
    unsigned long long d;
    asm("mov.b64 %0, {%1, %2};" : "=l"(d) : "r"(lo), "r"(hi));
    return d;
}
__device__ __forceinline__ void upk2(unsigned long long v, unsigned& lo, unsigned& hi) {
    asm("mov.b64 {%0, %1}, %2;" : "=r"(lo), "=r"(hi) : "l"(v));
}

// Diagonal-pair FFMA2 mm: W transposed [k][48], x [k][b] (row stride XS).
// Thread tile: 3 row-pairs x 1 batch-pair, KH k-iters.
template<int KH, int XS>
__device__ __forceinline__ void gate_mmT(const float* __restrict__ w,
                                         const float* __restrict__ xp,
                                         float* __restrict__ gp)
{
    unsigned long long d0=0ull, a0=0ull, d1=0ull, a1=0ull, d2=0ull, a2=0ull;
    #pragma unroll 5
    for (int k = 0; k < KH; ++k) {
        uint2 xv = *(const uint2*)(xp + k * XS);
        unsigned long long xd = pk2(xv.x, xv.y);
        unsigned long long xs = pk2(xv.y, xv.x);
        unsigned long long w0 = *(const unsigned long long*)(w + k * 48);
        unsigned long long w1 = *(const unsigned long long*)(w + k * 48 + 2);
        unsigned long long w2 = *(const unsigned long long*)(w + k * 48 + 4);
        FMA2(d0, w0, xd); FMA2(a0, w0, xs);
        FMA2(d1, w1, xd); FMA2(a1, w1, xs);
        FMA2(d2, w2, xd); FMA2(a2, w2, xs);
    }
    unsigned dl, dh, al, ah;
    upk2(d0, dl, dh); upk2(a0, al, ah);
    *(unsigned long long*)(gp + 0 * GRS) = pk2(dl, al);
    *(unsigned long long*)(gp + 1 * GRS) = pk2(ah, dh);
    upk2(d1, dl, dh); upk2(a1, al, ah);
    *(unsigned long long*)(gp + 2 * GRS) = pk2(dl, al);
    *(unsigned long long*)(gp + 3 * GRS) = pk2(ah, dh);
    upk2(d2, dl, dh); upk2(a2, al, ah);
    *(unsigned long long*)(gp + 4 * GRS) = pk2(dl, al);
    *(unsigned long long*)(gp + 5 * GRS) = pk2(ah, dh);
}

__global__ void __launch_bounds__(NTHR, 1)
lstm_all_kernel(const float* __restrict__ inp,  const float* __restrict__ h0in,
                const float* __restrict__ c0in,
                const float* __restrict__ Wih0, const float* __restrict__ Whh0,
                const float* __restrict__ bih0, const float* __restrict__ bhh0,
                const float* __restrict__ Wih1, const float* __restrict__ Whh1,
                const float* __restrict__ bih1, const float* __restrict__ bhh1,
                const float* __restrict__ fcW,  const float* __restrict__ fcb,
                float* __restrict__ out)
{
    extern __shared__ float sm[];
    float* W0t   = sm + OFF_W0;
    float* W1t   = sm + OFF_W1;
    float* xh    = sm + OFF_XH;
    float* gb0   = sm + OFF_GB0;
    float* gb1   = sm + OFF_GB1;
    float* bias0 = sm + OFF_B0;
    float* bias1 = sm + OFF_B1;
    float* c0s   = sm + OFF_C0;
    float* c1s   = sm + OFF_C1;

    const int tid = threadIdx.x;
    const int bg  = blockIdx.x / NHG;
    const int hg  = blockIdx.x % NHG;
    const int b0  = bg * MB;
    const int hs  = hg * NHU;
    const uint32_t smb = (uint32_t)__cvta_generic_to_shared(sm);

    const int cellA = tid & 63;
    const int bq2A  = cellA & 7;
    const int rpgA  = cellA >> 3;
    const int wofsA = 6 * rpgA;
    const int gofsA = 6 * rpgA * GRS + 2 * bq2A;
    const int ks1   = tid >> 6;            // layer1 ksplit (tid<512): 0..7
    const int tB    = tid - 512;
    const int cellB = tB & 63;
    const int bq2B  = cellB & 7;
    const int rpgB  = cellB >> 3;
    const int wofsB = 6 * rpgB;
    const int gofsB = 6 * rpgB * GRS + 2 * bq2B;
    const int ks0   = (tB >> 6) & 3;       // layer0 ksplit (tid>=512): 0..3

    // ---- resident weight slices (transposed [k][48]) ----
    for (int i = tid; i < NG * 300; i += NTHR) {
        int c = i / 300, k = i - c * 300;
        int gate = c / NHU, u = c - gate * NHU;
        int j = hs + u, row = gate * HID + j;
        float v = 0.f;
        if (j < HID) v = (k < INDIM) ? Wih0[row * INDIM + k] : Whh0[row * HID + (k - INDIM)];
        W0t[k * 48 + c] = v;
    }
    for (int i = tid; i < NG * 400; i += NTHR) {
        int c = i / 400, k = i - c * 400;
        int gate = c / NHU, u = c - gate * NHU;
        int j = hs + u, row = gate * HID + j;
        float v = 0.f;
        if (j < HID) v = (k < HID) ? Wih1[row * HID + k] : Whh1[row * HID + (k - HID)];
        W1t[k * 48 + c] = v;
    }
    if (tid < NG) {
        int gate = tid / NHU, u = tid - gate * NHU;
        int j = hs + u, row = gate * HID + j;
        bias0[tid] = (j < HID) ? bih0[row] + bhh0[row] : 0.f;
        bias1[tid] = (j < HID) ? bih1[row] + bhh1[row] : 0.f;
    }

    // ---- init c state, publish initial h ----
    if (tid < NHU * MB) {
        int e = tid, u = e >> 4, b = e & 15, j = hs + u;
        float cv0 = 0.f, cv1 = 0.f;
        if (j < HID) {
            cv0 = c0in[(b0 + b) * HID + j];
            cv1 = c0in[BATCH * HID + (b0 + b) * HID + j];
            g_ph0[1][j * BATCH + b0 + b] = h0in[(b0 + b) * HID + j];
            g_ph1[0][j * BATCH + b0 + b] = h0in[BATCH * HID + (b0 + b) * HID + j];
        }
        c0s[e] = cv0;
        c1s[e] = cv1;
    }
    __syncthreads();

    // ---- PRE-PASS: xp[t] = Wih0 . x_t for all t (6 timesteps per sweep) ----
    // thread: ttp = tid>>7 (0..5), ksp2 = (tid>>6)&1, cell = tid&63
    {
        const int ttp  = tid >> 7;
        const int ksp2 = (tid >> 6) & 1;
        float* gbp = gb0;                       // 12 x GBS partial area (gb0+gb1)
        for (int t0 = 0; t0 < T_STEPS; t0 += 6) {
            for (int idx = tid; idx < 6 * MB * INDIM; idx += NTHR) {
                int tt = idx / (MB * INDIM);
                int r  = idx - tt * (MB * INDIM);
                int b  = r / INDIM, k = r - b * INDIM;
                float v = 0.f;
                if (t0 + tt < T_STEPS)
                    v = __ldg(inp + (size_t)(t0 + tt) * (BATCH * INDIM)
                                  + (size_t)(b0 + b) * INDIM + k);
                xh[(tt * INDIM + k) * 16 + b] = v;
            }
            __syncthreads();
            gate_mmT<50, 16>(W0t + ksp2 * 50 * 48 + wofsA,
                             xh + (ttp * INDIM + ksp2 * 50) * 16 + 2 * bq2A,
                             gbp + (ttp * 2 + ksp2) * GBS + gofsA);
            __syncthreads();
            for (int idx = tid; idx < 6 * NG * MB; idx += NTHR) {
                int tt = idx / (NG * MB);
                int v  = idx - tt * (NG * MB);
                int r = v >> 4, b = v & 15;
                if (t0 + tt < T_STEPS) {
                    float s = gbp[(tt * 2 + 0) * GBS + r * GRS + b]
                            + gbp[(tt * 2 + 1) * GBS + r * GRS + b];
                    int gate = r / NHU, u = r - gate * NHU;
                    g_xp[((size_t)(t0 + tt) * XPROWS + gate * 204 + hs + u) * BATCH + b0 + b] = s;
                }
            }
            __syncthreads();
        }
    }

    unsigned* gbar = &g_bar[bg * 32];
    unsigned ep = 1;
    if (tid == 0) {
        bar_arrive(gbar);
        while (ld_acq(gbar) < ep * NHG) {}
    }
    __syncthreads();

    float xpr[4] = {0.f, 0.f, 0.f, 0.f};

    // ---- main loop: iter it = layer0(step it) + layer1(step it-1) ----
    for (int it = 0; it <= T_STEPS; ++it) {
        const float* ph0 = g_ph0[(it + 1) & 1];
        const float* ph1 = g_ph1[(it + 1) & 1];
        if (tid < 256 || tid >= 512) {
            int st = (tid < 256) ? tid : (tid - 256);   // 0..511
            for (int idx = st; idx < 800; idx += 512) {
                int a = idx >> 2, q = idx & 3;
                cpa16(smb + (OFF_XH + (INDIM + a) * XSTR + q * 4) * 4,
                      ph0 + a * BATCH + b0 + q * 4);
            }
            CPA_COMMIT();
            // prefetch this step's xp into registers (hidden behind cp.async/mm)
            if (it < T_STEPS && tid < 192) {
                const float* xpp = g_xp + ((size_t)it * XPROWS + hs + (tid >> 4)) * BATCH
                                        + b0 + (tid & 15);
                xpr[0] = __ldcg(xpp);
                xpr[1] = __ldcg(xpp + 204 * BATCH);
                xpr[2] = __ldcg(xpp + 408 * BATCH);
                xpr[3] = __ldcg(xpp + 612 * BATCH);
            }
            CPA_WAIT0();
            asm volatile("bar.sync 2, 512;" ::: "memory");
            if (tid < 256) {
                if (it >= 1)
                    gate_mmT<50, XSTR>(W1t + ks1 * 50 * 48 + wofsA,
                                       xh + (INDIM + ks1 * 50) * XSTR + 2 * bq2A,
                                       gb1 + ks1 * GBS + gofsA);
            } else {
                if (it < T_STEPS)
                    gate_mmT<50, XSTR>(W0t + (INDIM + ks0 * 50) * 48 + wofsB,
                                       xh + (INDIM + ks0 * 50) * XSTR + 2 * bq2B,
                                       gb0 + ks0 * GBS + gofsB);
            }
        } else {
            if (it >= 1) {
                int st = tid - 256;            // 0..255
                for (int idx = st; idx < 800; idx += 256) {
                    int a = idx >> 2, q = idx & 3;
                    cpa16(smb + (OFF_XH + (INDIM + HID + a) * XSTR + q * 4) * 4,
                          ph1 + a * BATCH + b0 + q * 4);
                }
            }
            CPA_COMMIT();
            CPA_WAIT0();
            asm volatile("bar.sync 3, 256;" ::: "memory");
            if (it >= 1)
                gate_mmT<50, XSTR>(W1t + ks1 * 50 * 48 + wofsA,
                                   xh + (INDIM + ks1 * 50) * XSTR + 2 * bq2A,
                                   gb1 + ks1 * GBS + gofsA);
        }
        __syncthreads();

        // ---- pointwise: layer0 tid<192 (gb0 + xpr regs), layer1 tid 256-447 ----
        if (it < T_STEPS && tid < 192) {
            int e = tid, u = e >> 4, b = e & 15, j = hs + u;
            float gv[4];
            #pragma unroll
            for (int g = 0; g < 4; ++g) {
                int rr = g * NHU + u;
                float v = bias0[rr] + xpr[g];
                #pragma unroll
                for (int s = 0; s < 4; ++s) v += gb0[s * GBS + rr * GRS + b];
                gv[g] = v;
            }
            float c = c0s[e];
            c = sigm(gv[1]) * c + sigm(gv[0]) * tanha(gv[2]);
            float h = sigm(gv[3]) * tanha(c);
            c0s[e] = c;
            if (j < HID) g_ph0[it & 1][j * BATCH + b0 + b] = h;
        }
        if (it >= 1 && tid >= 256 && tid < 448) {
            int e = tid - 256, u = e >> 4, b = e & 15, j = hs + u;
            float gv[4];
            #pragma unroll
            for (int g = 0; g < 4; ++g) {
                int rr = g * NHU + u;
                float v = bias1[rr];
                #pragma unroll
                for (int s = 0; s < 8; ++s) v += gb1[s * GBS + rr * GRS + b];
                gv[g] = v;
            }
            float c = c1s[e];
            c = sigm(gv[1]) * c + sigm(gv[0]) * tanha(gv[2]);
            float h = sigm(gv[3]) * tanha(c);
            c1s[e] = c;
            if (j < HID) {
                g_ph1[it & 1][j * BATCH + b0 + b] = h;
                g_y1[(size_t)(it - 1) * HID * BATCH + j * BATCH + b0 + b] = h;
            }
        }
        if (it == T_STEPS) break;
        __syncthreads();

        ep++;
        if (tid == 0) bar_arrive(gbar);
        if (tid == NTHR - 1) { while (ld_acq(gbar) < ep * NHG) {} }
        __syncthreads();
    }

    __syncthreads();

    // ---- epilogue: hn, cn ----
    if (tid < NHU * MB) {
        int e = tid, u = e >> 4, b = e & 15, j = hs + u;
        if (j < HID) {
            out[HN_OFF + (b0 + b) * HID + j]               = __ldcg(&g_ph0[(T_STEPS - 1) & 1][j * BATCH + b0 + b]);
            out[HN_OFF + BATCH * HID + (b0 + b) * HID + j] = __ldcg(&g_ph1[T_STEPS & 1][j * BATCH + b0 + b]);
            out[CN_OFF + (b0 + b) * HID + j]               = c0s[e];
            out[CN_OFF + BATCH * HID + (b0 + b) * HID + j] = c1s[e];
        }
    }
    __syncthreads();

    // ---- global barrier before FC ----
    if (tid == 0) {
        bar_arrive(&g_gbar);
        while (ld_acq(&g_gbar) < NCTA) {}
    }
    __syncthreads();

    // ---- FC phase: out[t,b,c] = fcb[c] + sum_h fcW[c][h] * y1[t,h,b] ----
    {
        float* fws = sm + OFF_FW;
        float* fbs = sm + OFF_FB;
        float* ys  = sm + OFF_YS;
        for (int i = tid; i < NCLS * HID; i += NTHR) fws[i] = fcW[i];
        if (tid < NCLS) fbs[tid] = fcb[tid];
        __syncthreads();

        const int bqf = (tid & 31) * 4;
        const int cg  = tid >> 5;              // 0..23
        for (int tt = 0; tt < 8; ++tt) {
            int t = blockIdx.x * 8 + tt;
            if (t >= T_STEPS) break;
            const float* y = g_y1 + (size_t)t * HID * BATCH;
            float acc[2][4][4];
            #pragma unroll
            for (int qi = 0; qi < 2; qi++) {
                int cq = cg + 24 * qi;
                #pragma unroll
                for (int jc = 0; jc < 4; jc++) {
                    float bv = (cq < 25) ? fbs[cq * 4 + jc] : 0.f;
                    #pragma unroll
                    for (int jb = 0; jb < 4; jb++) acc[qi][jc][jb] = bv;
                }
            }
            for (int kc = 0; kc < 4; ++kc) {
                __syncthreads();
                for (int i = tid; i < 50 * 32; i += NTHR) {
                    int k = i >> 5, q = i & 31;
                    *(float4*)&ys[k * 128 + q * 4] =
                        __ldcg((const float4*)(y + (size_t)(kc * 50 + k) * BATCH + q * 4));
                }
                __syncthreads();
                for (int k = 0; k < 50; ++k) {
                    float4 yv = *(const float4*)&ys[k * 128 + bqf];
                    #pragma unroll
                    for (int qi = 0; qi < 2; qi++) {
                        int cq = cg + 24 * qi;
                        if (cq < 25) {
                            #pragma unroll
                            for (int jc = 0; jc < 4; jc++) {
                                float w = fws[(cq * 4 + jc) * HID + kc * 50 + k];
                                acc[qi][jc][0] = fmaf(w, yv.x, acc[qi][jc][0]);
                                acc[qi][jc][1] = fmaf(w, yv.y, acc[qi][jc][1]);
                                acc[qi][jc][2] = fmaf(w, yv.z, acc[qi][jc][2]);
                                acc[qi][jc][3] = fmaf(w, yv.w, acc[qi][jc][3]);
                            }
                        }
                    }
                }
            }
            float* o = out + (size_t)t * BATCH * NCLS;
            #pragma unroll
            for (int qi = 0; qi < 2; qi++) {
                int cq = cg + 24 * qi;
                if (cq < 25) {
                    #pragma unroll
                    for (int jb = 0; jb < 4; jb++) {
                        float4 v = make_float4(acc[qi][0][jb], acc[qi][1][jb],
                                               acc[qi][2][jb], acc[qi][3][jb]);
                        *(float4*)(o + (bqf + jb) * NCLS + cq * 4) = v;
                    }
                }
            }
        }
    }

    // ---- reset-free counter cleanup ----
    __syncthreads();
    if (tid == 0) {
        bar_arrive(&g_ack);
        if (blockIdx.x == 0) {
            while (ld_acq(&g_ack) < NCTA) {}
            for (int i = 0; i < NBG; i++) *(volatile unsigned*)&g_bar[i * 32] = 0u;
            *(volatile unsigned*)&g_gbar = 0u;
            *(volatile unsigned*)&g_ack  = 0u;
        }
    }
}

extern "C" void kernel_launch(void* const* d_in, const int* in_sizes, int n_in,
                              void* d_out, int out_size)
{
    (void)in_sizes; (void)n_in; (void)out_size;
    const float* inp  = (const float*)d_in[0];
    const float* h0   = (const float*)d_in[1];
    const float* c0   = (const float*)d_in[2];
    const float* Wih0 = (const float*)d_in[3];
    const float* Whh0 = (const float*)d_in[4];
    const float* bih0 = (const float*)d_in[5];
    const float* bhh0 = (const float*)d_in[6];
    const float* Wih1 = (const float*)d_in[7];
    const float* Whh1 = (const float*)d_in[8];
    const float* bih1 = (const float*)d_in[9];
    const float* bhh1 = (const float*)d_in[10];
    const float* fcW  = (const float*)d_in[11];
    const float* fcb  = (const float*)d_in[12];
    float* out = (float*)d_out;

    cudaFuncSetAttribute(lstm_all_kernel,
                         cudaFuncAttributeMaxDynamicSharedMemorySize, SMEM_BYTES);
    lstm_all_kernel<<<NCTA, NTHR, SMEM_BYTES>>>(inp, h0, c0,
                                                Wih0, Whh0, bih0, bhh0,
                                                Wih1, Whh1, bih1, bhh1,
                                                fcW, fcb, out);
}

// round 15
// speedup vs baseline: 1.0242x; 1.0242x over previous
#include <cuda_runtime.h>
#include <cstdint>
#include <cstddef>

#define T_STEPS 1024
#define BATCH   128
#define INDIM   100
#define HID     200
#define NCLS    100
#define NBG     8
#define MB      16
#define NHG     17
#define NHU     12
#define NG      48
#define NTHR    768
#define NCTA    (NBG*NHG)   // 136
#define XSTR    20
#define GRS     18
#define GBS     (NG*GRS)    // 864
#define XPROWS  816         // 4 gates * 204

#define HN_OFF  (T_STEPS*BATCH*NCLS)
#define CN_OFF  (HN_OFF + 2*BATCH*HID)

// ---- smem float offsets ----
#define OFF_W0  0                        // W0 packed [150][12 rp][2k][2r]
#define OFF_W1  14400                    // W1 packed [200][12 rp][2k][2r]
#define OFF_XH  33600                    // [500][XSTR]; prepass reuses as [6][100][16]
#define OFF_GB0 43600                    // [4][GBS]; prepass uses [12][GBS] from here
#define OFF_GB1 47056                    // [8][GBS]
#define OFF_B0  57424
#define OFF_B1  57472
#define OFF_C0  57520
#define OFF_C1  57712
#define SMEM_FLOATS 57920
#define SMEM_BYTES  (SMEM_FLOATS*4)      // 231,680 B

// FC-phase smem reuse
#define OFF_FW  0
#define OFF_FB  20000
#define OFF_YS  20128

__device__ __align__(256) float g_ph0[2][HID*BATCH];
__device__ __align__(256) float g_ph1[2][HID*BATCH];
__device__ __align__(256) float g_y1[(size_t)T_STEPS*HID*BATCH];
__device__ __align__(256) float g_xp[(size_t)T_STEPS*XPROWS*BATCH];
__device__ unsigned g_bar[NBG*32];
__device__ unsigned g_gbar;
__device__ unsigned g_ack;

__device__ __forceinline__ float tanha(float x) {
    float r;
    asm("tanh.approx.f32 %0, %1;" : "=f"(r) : "f"(x));
    return r;
}
__device__ __forceinline__ float sigm(float x) {
    return fmaf(0.5f, tanha(0.5f * x), 0.5f);
}
__device__ __forceinline__ void bar_arrive(unsigned* p) {
    unsigned one = 1u;
    asm volatile("red.release.gpu.global.add.u32 [%0], %1;" :: "l"(p), "r"(one) : "memory");
}
__device__ __forceinline__ unsigned ld_acq(const unsigned* p) {
    unsigned v;
    asm volatile("ld.acquire.gpu.global.u32 %0, [%1];" : "=r"(v) : "l"(p) : "memory");
    return v;
}
__device__ __forceinline__ void cpa16(uint32_t dst, const void* src) {
    asm volatile("cp.async.cg.shared.global [%0], [%1], 16;" :: "r"(dst), "l"(src) : "memory");
}
#define CPA_COMMIT() asm volatile("cp.async.commit_group;" ::: "memory")
#define CPA_WAIT0()  asm volatile("cp.async.wait_group 0;" ::: "memory")

#define FMA2(acc, w, x) \
    asm("fma.rn.f32x2 %0, %1, %2, %0;" : "+l"(acc) : "l"(w), "l"(x))
__device__ __forceinline__ unsigned long long pk2(unsigned lo, unsigned hi) {
    unsigned long long d;
    asm("mov.b64 %0, {%1, %2};" : "=l"(d) : "r"(lo), "r"(hi));
    return d;
}
__device__ __forceinline__ void upk2(unsigned long long v, unsigned& lo, unsigned& hi) {
    asm("mov.b64 {%0, %1}, %2;" : "=r"(lo), "=r"(hi) : "l"(v));
}

// Packed-W diagonal-pair FFMA2 mm.
// W packed: Wq[(k>>1)*96 + (c>>1)*4 + (k&1)*2 + (c&1)]  (c = gate-row 0..47)
// One ulonglong2 load at w + kp*96 + m*4 gives BOTH k's row-pair operands:
//   .x = {w[2kp][2c2], w[2kp][2c2+1]},  .y = same for k=2kp+1.
// x [k][b] row stride XS; thread tile: 3 row-pairs x 1 batch-pair, KH even.
template<int KH, int XS>
__device__ __forceinline__ void gate_mmT(const float* __restrict__ w,
                                         const float* __restrict__ xp,
                                         float* __restrict__ gp)
{
    unsigned long long d0=0ull, a0=0ull, d1=0ull, a1=0ull, d2=0ull, a2=0ull;
    #pragma unroll 5
    for (int kp = 0; kp < KH/2; ++kp) {
        uint2 xv0 = *(const uint2*)(xp + (2*kp) * XS);
        uint2 xv1 = *(const uint2*)(xp + (2*kp+1) * XS);
        unsigned long long xd0 = pk2(xv0.x, xv0.y);
        unsigned long long xs0 = pk2(xv0.y, xv0.x);
        unsigned long long xd1 = pk2(xv1.x, xv1.y);
        unsigned long long xs1 = pk2(xv1.y, xv1.x);
        ulonglong2 wv0 = *(const ulonglong2*)(w + kp * 96);
        ulonglong2 wv1 = *(const ulonglong2*)(w + kp * 96 + 4);
        ulonglong2 wv2 = *(const ulonglong2*)(w + kp * 96 + 8);
        FMA2(d0, wv0.x, xd0); FMA2(a0, wv0.x, xs0);
        FMA2(d1, wv1.x, xd0); FMA2(a1, wv1.x, xs0);
        FMA2(d2, wv2.x, xd0); FMA2(a2, wv2.x, xs0);
        FMA2(d0, wv0.y, xd1); FMA2(a0, wv0.y, xs1);
        FMA2(d1, wv1.y, xd1); FMA2(a1, wv1.y, xs1);
        FMA2(d2, wv2.y, xd1); FMA2(a2, wv2.y, xs1);
    }
    unsigned dl, dh, al, ah;
    upk2(d0, dl, dh); upk2(a0, al, ah);
    *(unsigned long long*)(gp + 0 * GRS) = pk2(dl, al);
    *(unsigned long long*)(gp + 1 * GRS) = pk2(ah, dh);
    upk2(d1, dl, dh); upk2(a1, al, ah);
    *(unsigned long long*)(gp + 2 * GRS) = pk2(dl, al);
    *(unsigned long long*)(gp + 3 * GRS) = pk2(ah, dh);
    upk2(d2, dl, dh); upk2(a2, al, ah);
    *(unsigned long long*)(gp + 4 * GRS) = pk2(dl, al);
    *(unsigned long long*)(gp + 5 * GRS) = pk2(ah, dh);
}

__global__ void __launch_bounds__(NTHR, 1)
lstm_all_kernel(const float* __restrict__ inp,  const float* __restrict__ h0in,
                const float* __restrict__ c0in,
                const float* __restrict__ Wih0, const float* __restrict__ Whh0,
                const float* __restrict__ bih0, const float* __restrict__ bhh0,
                const float* __restrict__ Wih1, const float* __restrict__ Whh1,
                const float* __restrict__ bih1, const float* __restrict__ bhh1,
                const float* __restrict__ fcW,  const float* __restrict__ fcb,
                float* __restrict__ out)
{
    extern __shared__ float sm[];
    float* W0t   = sm + OFF_W0;
    float* W1t   = sm + OFF_W1;
    float* xh    = sm + OFF_XH;
    float* gb0   = sm + OFF_GB0;
    float* gb1   = sm + OFF_GB1;
    float* bias0 = sm + OFF_B0;
    float* bias1 = sm + OFF_B1;
    float* c0s   = sm + OFF_C0;
    float* c1s   = sm + OFF_C1;

    const int tid = threadIdx.x;
    const int bg  = blockIdx.x / NHG;
    const int hg  = blockIdx.x % NHG;
    const int b0  = bg * MB;
    const int hs  = hg * NHU;
    const uint32_t smb = (uint32_t)__cvta_generic_to_shared(sm);

    const int cellA = tid & 63;
    const int bq2A  = cellA & 7;
    const int rpgA  = cellA >> 3;
    const int wofsA = 12 * rpgA;           // packed: row-pair block (3rpg)*4
    const int gofsA = 6 * rpgA * GRS + 2 * bq2A;
    const int ks1   = tid >> 6;
    const int tB    = tid - 512;
    const int cellB = tB & 63;
    const int bq2B  = cellB & 7;
    const int rpgB  = cellB >> 3;
    const int wofsB = 12 * rpgB;
    const int gofsB = 6 * rpgB * GRS + 2 * bq2B;
    const int ks0   = (tB >> 6) & 3;

    // ---- resident weight slices (k-pair/row-pair packed) ----
    for (int i = tid; i < NG * 300; i += NTHR) {
        int c = i / 300, k = i - c * 300;
        int gate = c / NHU, u = c - gate * NHU;
        int j = hs + u, row = gate * HID + j;
        float v = 0.f;
        if (j < HID) v = (k < INDIM) ? Wih0[row * INDIM + k] : Whh0[row * HID + (k - INDIM)];
        W0t[(k >> 1) * 96 + (c >> 1) * 4 + (k & 1) * 2 + (c & 1)] = v;
    }
    for (int i = tid; i < NG * 400; i += NTHR) {
        int c = i / 400, k = i - c * 400;
        int gate = c / NHU, u = c - gate * NHU;
        int j = hs + u, row = gate * HID + j;
        float v = 0.f;
        if (j < HID) v = (k < HID) ? Wih1[row * HID + k] : Whh1[row * HID + (k - HID)];
        W1t[(k >> 1) * 96 + (c >> 1) * 4 + (k & 1) * 2 + (c & 1)] = v;
    }
    if (tid < NG) {
        int gate = tid / NHU, u = tid - gate * NHU;
        int j = hs + u, row = gate * HID + j;
        bias0[tid] = (j < HID) ? bih0[row] + bhh0[row] : 0.f;
        bias1[tid] = (j < HID) ? bih1[row] + bhh1[row] : 0.f;
    }

    // ---- init c state, publish initial h ----
    if (tid < NHU * MB) {
        int e = tid, u = e >> 4, b = e & 15, j = hs + u;
        float cv0 = 0.f, cv1 = 0.f;
        if (j < HID) {
            cv0 = c0in[(b0 + b) * HID + j];
            cv1 = c0in[BATCH * HID + (b0 + b) * HID + j];
            g_ph0[1][j * BATCH + b0 + b] = h0in[(b0 + b) * HID + j];
            g_ph1[0][j * BATCH + b0 + b] = h0in[BATCH * HID + (b0 + b) * HID + j];
        }
        c0s[e] = cv0;
        c1s[e] = cv1;
    }
    __syncthreads();

    // ---- PRE-PASS: xp[t] = Wih0 . x_t for all t (6 timesteps per sweep) ----
    {
        const int ttp  = tid >> 7;
        const int ksp2 = (tid >> 6) & 1;
        float* gbp = gb0;
        for (int t0 = 0; t0 < T_STEPS; t0 += 6) {
            for (int idx = tid; idx < 6 * MB * INDIM; idx += NTHR) {
                int tt = idx / (MB * INDIM);
                int r  = idx - tt * (MB * INDIM);
                int b  = r / INDIM, k = r - b * INDIM;
                float v = 0.f;
                if (t0 + tt < T_STEPS)
                    v = __ldg(inp + (size_t)(t0 + tt) * (BATCH * INDIM)
                                  + (size_t)(b0 + b) * INDIM + k);
                xh[(tt * INDIM + k) * 16 + b] = v;
            }
            __syncthreads();
            gate_mmT<50, 16>(W0t + ksp2 * 50 * 48 + wofsA,
                             xh + (ttp * INDIM + ksp2 * 50) * 16 + 2 * bq2A,
                             gbp + (ttp * 2 + ksp2) * GBS + gofsA);
            __syncthreads();
            for (int idx = tid; idx < 6 * NG * MB; idx += NTHR) {
                int tt = idx / (NG * MB);
                int v  = idx - tt * (NG * MB);
                int r = v >> 4, b = v & 15;
                if (t0 + tt < T_STEPS) {
                    float s = gbp[(tt * 2 + 0) * GBS + r * GRS + b]
                            + gbp[(tt * 2 + 1) * GBS + r * GRS + b];
                    int gate = r / NHU, u = r - gate * NHU;
                    g_xp[((size_t)(t0 + tt) * XPROWS + gate * 204 + hs + u) * BATCH + b0 + b] = s;
                }
            }
            __syncthreads();
        }
    }

    unsigned* gbar = &g_bar[bg * 32];
    unsigned ep = 1;
    if (tid == 0) {
        bar_arrive(gbar);
        while (ld_acq(gbar) < ep * NHG) {}
    }
    __syncthreads();

    float xpr[4] = {0.f, 0.f, 0.f, 0.f};

    // ---- main loop: iter it = layer0(step it) + layer1(step it-1) ----
    for (int it = 0; it <= T_STEPS; ++it) {
        const float* ph0 = g_ph0[(it + 1) & 1];
        const float* ph1 = g_ph1[(it + 1) & 1];
        if (tid < 256 || tid >= 512) {
            int st = (tid < 256) ? tid : (tid - 256);
            for (int idx = st; idx < 800; idx += 512) {
                int a = idx >> 2, q = idx & 3;
                cpa16(smb + (OFF_XH + (INDIM + a) * XSTR + q * 4) * 4,
                      ph0 + a * BATCH + b0 + q * 4);
            }
            CPA_COMMIT();
            if (it < T_STEPS && tid < 192) {
                const float* xpp = g_xp + ((size_t)it * XPROWS + hs + (tid >> 4)) * BATCH
                                        + b0 + (tid & 15);
                xpr[0] = __ldcg(xpp);
                xpr[1] = __ldcg(xpp + 204 * BATCH);
                xpr[2] = __ldcg(xpp + 408 * BATCH);
                xpr[3] = __ldcg(xpp + 612 * BATCH);
            }
            CPA_WAIT0();
            asm volatile("bar.sync 2, 512;" ::: "memory");
            if (tid < 256) {
                if (it >= 1)
                    gate_mmT<50, XSTR>(W1t + ks1 * 50 * 48 + wofsA,
                                       xh + (INDIM + ks1 * 50) * XSTR + 2 * bq2A,
                                       gb1 + ks1 * GBS + gofsA);
            } else {
                if (it < T_STEPS)
                    gate_mmT<50, XSTR>(W0t + (INDIM + ks0 * 50) * 48 + wofsB,
                                       xh + (INDIM + ks0 * 50) * XSTR + 2 * bq2B,
                                       gb0 + ks0 * GBS + gofsB);
            }
        } else {
            if (it >= 1) {
                int st = tid - 256;
                for (int idx = st; idx < 800; idx += 256) {
                    int a = idx >> 2, q = idx & 3;
                    cpa16(smb + (OFF_XH + (INDIM + HID + a) * XSTR + q * 4) * 4,
                          ph1 + a * BATCH + b0 + q * 4);
                }
            }
            CPA_COMMIT();
            CPA_WAIT0();
            asm volatile("bar.sync 3, 256;" ::: "memory");
            if (it >= 1)
                gate_mmT<50, XSTR>(W1t + ks1 * 50 * 48 + wofsA,
                                   xh + (INDIM + ks1 * 50) * XSTR + 2 * bq2A,
                                   gb1 + ks1 * GBS + gofsA);
        }
        __syncthreads();

        // ---- pointwise ----
        if (it < T_STEPS && tid < 192) {
            int e = tid, u = e >> 4, b = e & 15, j = hs + u;
            float gv[4];
            #pragma unroll
            for (int g = 0; g < 4; ++g) {
                int rr = g * NHU + u;
                float v = bias0[rr] + xpr[g];
                #pragma unroll
                for (int s = 0; s < 4; ++s) v += gb0[s * GBS + rr * GRS + b];
                gv[g] = v;
            }
            float c = c0s[e];
            c = sigm(gv[1]) * c + sigm(gv[0]) * tanha(gv[2]);
            float h = sigm(gv[3]) * tanha(c);
            c0s[e] = c;
            if (j < HID) g_ph0[it & 1][j * BATCH + b0 + b] = h;
        }
        if (it >= 1 && tid >= 256 && tid < 448) {
            int e = tid - 256, u = e >> 4, b = e & 15, j = hs + u;
            float gv[4];
            #pragma unroll
            for (int g = 0; g < 4; ++g) {
                int rr = g * NHU + u;
                float v = bias1[rr];
                #pragma unroll
                for (int s = 0; s < 8; ++s) v += gb1[s * GBS + rr * GRS + b];
                gv[g] = v;
            }
            float c = c1s[e];
            c = sigm(gv[1]) * c + sigm(gv[0]) * tanha(gv[2]);
            float h = sigm(gv[3]) * tanha(c);
            c1s[e] = c;
            if (j < HID) {
                g_ph1[it & 1][j * BATCH + b0 + b] = h;
                g_y1[(size_t)(it - 1) * HID * BATCH + j * BATCH + b0 + b] = h;
            }
        }
        if (it == T_STEPS) break;
        __syncthreads();

        ep++;
        if (tid == 0) bar_arrive(gbar);
        if (tid == NTHR - 1) { while (ld_acq(gbar) < ep * NHG) {} }
        __syncthreads();
    }

    __syncthreads();

    // ---- epilogue: hn, cn ----
    if (tid < NHU * MB) {
        int e = tid, u = e >> 4, b = e & 15, j = hs + u;
        if (j < HID) {
            out[HN_OFF + (b0 + b) * HID + j]               = __ldcg(&g_ph0[(T_STEPS - 1) & 1][j * BATCH + b0 + b]);
            out[HN_OFF + BATCH * HID + (b0 + b) * HID + j] = __ldcg(&g_ph1[T_STEPS & 1][j * BATCH + b0 + b]);
            out[CN_OFF + (b0 + b) * HID + j]               = c0s[e];
            out[CN_OFF + BATCH * HID + (b0 + b) * HID + j] = c1s[e];
        }
    }
    __syncthreads();

    if (tid == 0) {
        bar_arrive(&g_gbar);
        while (ld_acq(&g_gbar) < NCTA) {}
    }
    __syncthreads();

    // ---- FC phase ----
    {
        float* fws = sm + OFF_FW;
        float* fbs = sm + OFF_FB;
        float* ys  = sm + OFF_YS;
        for (int i = tid; i < NCLS * HID; i += NTHR) fws[i] = fcW[i];
        if (tid < NCLS) fbs[tid] = fcb[tid];
        __syncthreads();

        const int bqf = (tid & 31) * 4;
        const int cg  = tid >> 5;
        for (int tt = 0; tt < 8; ++tt) {
            int t = blockIdx.x * 8 + tt;
            if (t >= T_STEPS) break;
            const float* y = g_y1 + (size_t)t * HID * BATCH;
            float acc[2][4][4];
            #pragma unroll
            for (int qi = 0; qi < 2; qi++) {
                int cq = cg + 24 * qi;
                #pragma unroll
                for (int jc = 0; jc < 4; jc++) {
                    float bv = (cq < 25) ? fbs[cq * 4 + jc] : 0.f;
                    #pragma unroll
                    for (int jb = 0; jb < 4; jb++) acc[qi][jc][jb] = bv;
                }
            }
            for (int kc = 0; kc < 4; ++kc) {
                __syncthreads();
                for (int i = tid; i < 50 * 32; i += NTHR) {
                    int k = i >> 5, q = i & 31;
                    *(float4*)&ys[k * 128 + q * 4] =
                        __ldcg((const float4*)(y + (size_t)(kc * 50 + k) * BATCH + q * 4));
                }
                __syncthreads();
                for (int k = 0; k < 50; ++k) {
                    float4 yv = *(const float4*)&ys[k * 128 + bqf];
                    #pragma unroll
                    for (int qi = 0; qi < 2; qi++) {
                        int cq = cg + 24 * qi;
                        if (cq < 25) {
                            #pragma unroll
                            for (int jc = 0; jc < 4; jc++) {
                                float w = fws[(cq * 4 + jc) * HID + kc * 50 + k];
                                acc[qi][jc][0] = fmaf(w, yv.x, acc[qi][jc][0]);
                                acc[qi][jc][1] = fmaf(w, yv.y, acc[qi][jc][1]);
                                acc[qi][jc][2] = fmaf(w, yv.z, acc[qi][jc][2]);
                                acc[qi][jc][3] = fmaf(w, yv.w, acc[qi][jc][3]);
                            }
                        }
                    }
                }
            }
            float* o = out + (size_t)t * BATCH * NCLS;
            #pragma unroll
            for (int qi = 0; qi < 2; qi++) {
                int cq = cg + 24 * qi;
                if (cq < 25) {
                    #pragma unroll
                    for (int jb = 0; jb < 4; jb++) {
                        float4 v = make_float4(acc[qi][0][jb], acc[qi][1][jb],
                                               acc[qi][2][jb], acc[qi][3][jb]);
                        *(float4*)(o + (bqf + jb) * NCLS + cq * 4) = v;
                    }
                }
            }
        }
    }

    __syncthreads();
    if (tid == 0) {
        bar_arrive(&g_ack);
        if (blockIdx.x == 0) {
            while (ld_acq(&g_ack) < NCTA) {}
            for (int i = 0; i < NBG; i++) *(volatile unsigned*)&g_bar[i * 32] = 0u;
            *(volatile unsigned*)&g_gbar = 0u;
            *(volatile unsigned*)&g_ack  = 0u;
        }
    }
}

extern "C" void kernel_launch(void* const* d_in, const int* in_sizes, int n_in,
                              void* d_out, int out_size)
{
    (void)in_sizes; (void)n_in; (void)out_size;
    const float* inp  = (const float*)d_in[0];
    const float* h0   = (const float*)d_in[1];
    const float* c0   = (const float*)d_in[2];
    const float* Wih0 = (const float*)d_in[3];
    const float* Whh0 = (const float*)d_in[4];
    const float* bih0 = (const float*)d_in[5];
    const float* bhh0 = (const float*)d_in[6];
    const float* Wih1 = (const float*)d_in[7];
    const float* Whh1 = (const float*)d_in[8];
    const float* bih1 = (const float*)d_in[9];
    const float* bhh1 = (const float*)d_in[10];
    const float* fcW  = (const float*)d_in[11];
    const float* fcb  = (const float*)d_in[12];
    float* out = (float*)d_out;

    cudaFuncSetAttribute(lstm_all_kernel,
                         cudaFuncAttributeMaxDynamicSharedMemorySize, SMEM_BYTES);
    lstm_all_kernel<<<NCTA, NTHR, SMEM_BYTES>>>(inp, h0, c0,
                                                Wih0, Whh0, bih0, bhh0,
                                                Wih1, Whh1, bih1, bhh1,
                                                fcW, fcb, out);
}